// round 1
// baseline (speedup 1.0000x reference)
#include <cuda_runtime.h>

#define PP 32
#define SS 4
#define HH 256
#define WW 256
#define HW (HH*WW)          // 65536
#define NPIX (SS*HW)        // 262144  (per-plane pixels across all s)
#define NOUT (PP*SS*HW)     // 8388608 output pixels (x10 channels)

// Scratch: per (p,s,pixel): {over.r, over.g, over.b, T}
__device__ float4 g_data[PP * SS * HW];          // 134 MB
// Per (p,s): affine warp coeffs: M(3x3, includes *depth) then b(3)
__device__ float  g_warp[PP * SS * 12];

// ---------------------------------------------------------------------------
// Kernel 0: tiny per-(p,s) warp-matrix precompute.
// upc = (Ksrc @ pose[:3,:3] @ Kinv_tgt * depth) @ [x,y,1] + Ksrc @ pose[:3,3]
// ---------------------------------------------------------------------------
__global__ void precompute_kernel(const float* __restrict__ mpi_planes,
                                  const float* __restrict__ pose_tgt,
                                  const float* __restrict__ intrins_src,
                                  const float* __restrict__ intrins_tgt)
{
    int b = blockIdx.x * blockDim.x + threadIdx.x;
    if (b >= PP * SS) return;
    int p = b / SS, s = b % SS;

    float Kt[9];
    #pragma unroll
    for (int i = 0; i < 9; i++) Kt[i] = intrins_tgt[i];
    float det = Kt[0]*(Kt[4]*Kt[8]-Kt[5]*Kt[7])
              - Kt[1]*(Kt[3]*Kt[8]-Kt[5]*Kt[6])
              + Kt[2]*(Kt[3]*Kt[7]-Kt[4]*Kt[6]);
    float id = 1.0f / det;
    float inv[9];
    inv[0]=(Kt[4]*Kt[8]-Kt[5]*Kt[7])*id;
    inv[1]=(Kt[2]*Kt[7]-Kt[1]*Kt[8])*id;
    inv[2]=(Kt[1]*Kt[5]-Kt[2]*Kt[4])*id;
    inv[3]=(Kt[5]*Kt[6]-Kt[3]*Kt[8])*id;
    inv[4]=(Kt[0]*Kt[8]-Kt[2]*Kt[6])*id;
    inv[5]=(Kt[2]*Kt[3]-Kt[0]*Kt[5])*id;
    inv[6]=(Kt[3]*Kt[7]-Kt[4]*Kt[6])*id;
    inv[7]=(Kt[1]*Kt[6]-Kt[0]*Kt[7])*id;
    inv[8]=(Kt[0]*Kt[4]-Kt[1]*Kt[3])*id;

    const float* Ks   = intrins_src + s * 9;
    const float* pose = pose_tgt   + s * 16;

    // A = Ksrc @ pose[:3,:3]; bb = Ksrc @ pose[:3,3]
    float A[9], bb[3];
    #pragma unroll
    for (int i = 0; i < 3; i++) {
        #pragma unroll
        for (int j = 0; j < 3; j++) {
            float acc = 0.f;
            #pragma unroll
            for (int k = 0; k < 3; k++) acc += Ks[i*3+k] * pose[k*4+j];
            A[i*3+j] = acc;
        }
        float accb = 0.f;
        #pragma unroll
        for (int k = 0; k < 3; k++) accb += Ks[i*3+k] * pose[k*4+3];
        bb[i] = accb;
    }

    float d = mpi_planes[p];
    float* w = g_warp + b * 12;
    #pragma unroll
    for (int i = 0; i < 3; i++)
        #pragma unroll
        for (int j = 0; j < 3; j++) {
            float acc = 0.f;
            #pragma unroll
            for (int k = 0; k < 3; k++) acc += A[i*3+k] * inv[k*3+j];
            w[i*3+j] = acc * d;
        }
    w[9] = bb[0]; w[10] = bb[1]; w[11] = bb[2];
}

// ---------------------------------------------------------------------------
// Kernel 1: per-(s,pixel) scan over the 32 planes.
// Writes float4 {over.rgb, T[p]} per plane.
// ---------------------------------------------------------------------------
__global__ void __launch_bounds__(256)
pass1_kernel(const float* __restrict__ colors,
             const float* __restrict__ alphas)
{
    int idx = blockIdx.x * blockDim.x + threadIdx.x;   // s*HW + pix
    if (idx >= NPIX) return;

    float a[PP];
    #pragma unroll
    for (int p = 0; p < PP; p++)
        a[p] = __ldg(alphas + p * NPIX + idx);

    // suffix transmittance: T[p] = prod_{j>p} (1 - a[j])
    float T[PP];
    float t = 1.0f;
    #pragma unroll
    for (int p = PP - 1; p >= 0; p--) { T[p] = t; t *= (1.0f - a[p]); }

    float ox = 0.f, oy = 0.f, oz = 0.f;
    #pragma unroll
    for (int p = 0; p < PP; p++) {
        const float* c = colors + (long)(p * NPIX + idx) * 3;
        float ap  = a[p];
        float cap = 1.0f - ap;
        ox = fmaf(ox, cap, __ldg(c + 0) * ap);
        oy = fmaf(oy, cap, __ldg(c + 1) * ap);
        oz = fmaf(oz, cap, __ldg(c + 2) * ap);
        g_data[p * NPIX + idx] = make_float4(ox, oy, oz, T[p]);
    }
}

// ---------------------------------------------------------------------------
// Kernel 2: warp + bilinear gather + write (P,S,10,H,W).
// ---------------------------------------------------------------------------
__global__ void __launch_bounds__(256)
pass2_kernel(const float* __restrict__ imgs_src,
             float* __restrict__ out)
{
    int idx = blockIdx.x * blockDim.x + threadIdx.x;   // [0, NOUT)
    if (idx >= NOUT) return;

    int pix = idx & (HW - 1);
    int ps  = idx >> 16;          // HW = 2^16
    int s   = ps & (SS - 1);
    int p   = ps >> 2;            // SS = 4

    float fx = (float)(pix & (WW - 1));
    float fy = (float)(pix >> 8);

    const float* w = g_warp + ps * 12;   // uniform per block (HW % 256 == 0)
    float u0 = fmaf(w[0], fx, fmaf(w[1], fy, w[2]))  + w[9];
    float u1 = fmaf(w[3], fx, fmaf(w[4], fy, w[5]))  + w[10];
    float u2 = fmaf(w[6], fx, fmaf(w[7], fy, w[8]))  + w[11];
    float z  = u2 + 1e-10f;
    float ix = u0 / z;
    float iy = u1 / z;

    float x0f = floorf(ix), y0f = floorf(iy);
    float wx1 = ix - x0f, wy1 = iy - y0f;
    float wx0 = 1.0f - wx1, wy0 = 1.0f - wy1;

    int   kacc   = (p >= 2) ? (p - 2) : 0;
    const int basep = ps * HW;                       // plane p, seq s
    const int basea = (kacc * SS + s) * HW;          // acc plane
    const int baseb = ((PP - 1) * SS + s) * HW;      // last plane (bro)
    const int bases = s * HW;                        // src image

    float o[10];
    #pragma unroll
    for (int c = 0; c < 10; c++) o[c] = 0.f;

    #pragma unroll
    for (int cy = 0; cy < 2; cy++) {
        float yyf = y0f + (float)cy;
        float wy  = cy ? wy1 : wy0;
        #pragma unroll
        for (int cx = 0; cx < 2; cx++) {
            float xxf = x0f + (float)cx;
            bool valid = (xxf >= 0.f) & (xxf <= (float)(WW - 1)) &
                         (yyf >= 0.f) & (yyf <= (float)(HH - 1));
            if (!valid) continue;
            float wgt = (cx ? wx1 : wx0) * wy;
            int xc = (int)xxf;
            int yc = (int)yyf;
            int off = yc * WW + xc;

            float4 fT = __ldg(&g_data[basep + off]);   // .w = T[p]
            float4 fA = __ldg(&g_data[basea + off]);   // .xyz = acc
            float4 fB = __ldg(&g_data[baseb + off]);   // .xyz = bro (L2-resident)
            const float* sp = imgs_src + (long)(bases + off) * 3;

            o[0] = fmaf(wgt, fT.w, o[0]);
            o[1] = fmaf(wgt, fA.x, o[1]);
            o[2] = fmaf(wgt, fA.y, o[2]);
            o[3] = fmaf(wgt, fA.z, o[3]);
            o[4] = fmaf(wgt, fB.x, o[4]);
            o[5] = fmaf(wgt, fB.y, o[5]);
            o[6] = fmaf(wgt, fB.z, o[6]);
            o[7] = fmaf(wgt, __ldg(sp + 0), o[7]);
            o[8] = fmaf(wgt, __ldg(sp + 1), o[8]);
            o[9] = fmaf(wgt, __ldg(sp + 2), o[9]);
        }
    }

    #pragma unroll
    for (int c = 0; c < 10; c++)
        out[(ps * 10 + c) * HW + pix] = o[c];
}

// ---------------------------------------------------------------------------
extern "C" void kernel_launch(void* const* d_in, const int* in_sizes, int n_in,
                              void* d_out, int out_size)
{
    const float* colors      = (const float*)d_in[0];  // (P,S,H,W,3)
    const float* alphas      = (const float*)d_in[1];  // (P,S,H,W)
    const float* imgs_src    = (const float*)d_in[2];  // (S,H,W,3)
    const float* mpi_planes  = (const float*)d_in[3];  // (P,)
    const float* pose_tgt    = (const float*)d_in[4];  // (S,4,4)
    const float* intrins_src = (const float*)d_in[5];  // (S,3,3)
    const float* intrins_tgt = (const float*)d_in[6];  // (3,3)
    float* out = (float*)d_out;                        // (P,S,10,H,W)

    precompute_kernel<<<1, 128>>>(mpi_planes, pose_tgt, intrins_src, intrins_tgt);
    pass1_kernel<<<NPIX / 256, 256>>>(colors, alphas);
    pass2_kernel<<<NOUT / 256, 256>>>(imgs_src, out);
}